// round 7
// baseline (speedup 1.0000x reference)
#include <cuda_runtime.h>
#include <math.h>

#define H_FIXED 16
#define K_FIXED 5
#define MAX_S 4096
#define L4_OF(S) (2 * (S) + 4)              // per-head padded length (multiple of 4)
#define MAX_L4 (2 * MAX_S + 4)

// 4 phase-shifted copies of the reversed scores table:
//   T[a][h][m] = revsc[h][m + a],  revsc[h][q] = scores[h][2S - q]
// Reading T[a] starting at aligned element (idx0 - a), where a = idx0 & 3,
// yields revsc[idx0 + m] with 16B-aligned float4 loads.
__device__ __align__(16) float g_tab[4 * H_FIXED * MAX_L4];

// Kernel 1: compute revsc[h][q], scatter into the 4 phase copies.
__global__ void tisa_scores_kernel(const float* __restrict__ off,
                                   const float* __restrict__ wid,
                                   const float* __restrict__ amp,
                                   int S) {
    const int L = 2 * S + 1;
    const int total = H_FIXED * L;
    int idx = blockIdx.x * blockDim.x + threadIdx.x;
    if (idx >= total) return;
    int h = idx / L;
    int q = idx - h * L;
    float rel = (float)(S - q);            // revsc[q] = scores[2S - q]
    float sum = 0.0f;
#pragma unroll
    for (int k = 0; k < K_FIXED; k++) {
        float o = off[k * H_FIXED + h];
        float w = fabsf(wid[k * H_FIXED + h]);
        float a = amp[k * H_FIXED + h];
        float d = o - rel;
        sum += a * expf(-w * d * d);
    }
    const int L4 = L4_OF(S);
#pragma unroll
    for (int a = 0; a < 4; a++) {
        int m = q - a;                      // T[a][h][m] = revsc[h][m + a]
        if (m >= 0)
            g_tab[((size_t)a * H_FIXED + h) * L4 + m] = sum;
    }
}

// Kernel 2: register-cached row-group expansion.
// Each thread loads V[0..19] = revsc[idx0 .. idx0+19] (5 aligned float4 LDG),
// then emits the same float4 column for 16 consecutive rows:
//   out[h, i0+r, j..j+3] = revsc[S+1-(i0+r)+j .. +3] = V[15-r .. 18-r]
// Load wavefronts amortized 16x: ~1.31 L1 wavefronts per 128B output.
#define R_ROWS 16
#define TPB 256

__global__ void tisa_expand_kernel(float4* __restrict__ out, int S) {
    const int h  = blockIdx.z;
    const int i0 = blockIdx.y * R_ROWS;
    const int j4 = blockIdx.x * TPB + threadIdx.x;   // float4 column index
    const int S4 = S >> 2;
    if (j4 >= S4) return;
    const int j = j4 << 2;

    // lowest source index needed by this thread across the 16 rows
    const int idx0 = (S + 1) - (i0 + R_ROWS - 1) + j; // = S - 14 - i0 + j
    const int a = idx0 & 3;                           // uniform within block
    const int L4 = L4_OF(S);
    const float4* __restrict__ T =
        (const float4*)(g_tab + ((size_t)a * H_FIXED + h) * L4 + (idx0 - a));

    float v[R_ROWS + 4];
#pragma unroll
    for (int p = 0; p < (R_ROWS + 4) / 4; p++) {      // 5 aligned float4 loads
        float4 t = __ldg(T + p);                      // t = revsc[idx0 + 4p ..]
        v[p * 4 + 0] = t.x;
        v[p * 4 + 1] = t.y;
        v[p * 4 + 2] = t.z;
        v[p * 4 + 3] = t.w;
    }

    float4* __restrict__ dst = out + ((size_t)h * S + i0) * (size_t)S4 + j4;
#pragma unroll
    for (int r = 0; r < R_ROWS; r++) {
        int k = (R_ROWS - 1) - r;                     // 15 - r
        float4 o;
        o.x = v[k + 0];
        o.y = v[k + 1];
        o.z = v[k + 2];
        o.w = v[k + 3];
        dst[(size_t)r * S4] = o;
    }
}

extern "C" void kernel_launch(void* const* d_in, const int* in_sizes, int n_in,
                              void* d_out, int out_size) {
    // Inputs (metadata order): seq_len (scalar, unused), offsets [K,H],
    // widths [K,H], amplitudes [K,H]
    const float* off = (const float*)d_in[1];
    const float* wid = (const float*)d_in[2];
    const float* amp = (const float*)d_in[3];

    // out_size = H * S * S; H = 16 fixed for this problem
    int S = (int)llround(sqrt((double)out_size / (double)H_FIXED));

    // Kernel 1: phase-shifted table build
    {
        int total = H_FIXED * (2 * S + 1);
        int threads = 256;
        int blocks = (total + threads - 1) / threads;
        tisa_scores_kernel<<<blocks, threads>>>(off, wid, amp, S);
    }

    // Kernel 2: register-amortized Toeplitz expansion
    {
        int S4 = S >> 2;
        dim3 grid((S4 + TPB - 1) / TPB, S / R_ROWS, H_FIXED);
        tisa_expand_kernel<<<grid, TPB>>>((float4*)d_out, S);
    }
}